// round 5
// baseline (speedup 1.0000x reference)
#include <cuda_runtime.h>
#include <math.h>

#define NB 256        // batch
#define NT 64         // timesteps
#define NACT 6
#define GDIM 3072
#define ZA_LD 1040    // 1024 z + 6 act + 10 zero pad (K=1040 multiple of 16)
#define WI1_K 1040

// ---------------- scratch (device globals: no allocation allowed) ----------------
__device__ float g_ZA[NB * ZA_LD];       // [z (1024) | action (6) | zero pad]
__device__ float g_H1[NB * 1024];        // imagine hidden
__device__ float g_IB[NB * 2048];        // [inp (1024) | belief (1024)]
__device__ float g_G [NB * GDIM];        // raw GRU gates
__device__ float g_HP[NB * 1024];        // prior hidden
__device__ float g_HO[NB * 1024];        // post hidden
__device__ float g_PL[NB * 1024];        // prior logits
__device__ float g_QL[NB * 1024];        // post logits
__device__ float g_Wi1p[WI1_K * 1024];   // Wi1 zero-padded to K=1040 rows

// ---------------- helpers ----------------
__device__ __forceinline__ float warp_sum(float v) {
#pragma unroll
    for (int o = 16; o; o >>= 1) v += __shfl_xor_sync(0xffffffffu, v, o);
    return v;
}
__device__ __forceinline__ float warp_max(float v) {
#pragma unroll
    for (int o = 16; o; o >>= 1) v = fmaxf(v, __shfl_xor_sync(0xffffffffu, v, o));
    return v;
}

// precise transcendentals via double path (immune to --use_fast_math rewrites)
__device__ __forceinline__ float silu_f(float x) {
    double e = exp(-(double)x);
    return (float)((double)x / (1.0 + e));
}
__device__ __forceinline__ float sigmoid_f(float x) {
    return (float)(1.0 / (1.0 + exp(-(double)x)));
}

// ---------------- packed f32x2 via PTX (per-lane identical to FFMA rounding) ----
__device__ __forceinline__ double dup2(float x) {
    double r; asm("mov.b64 %0, {%1,%1};" : "=d"(r) : "f"(x)); return r;
}
__device__ __forceinline__ double ffma2(double a, double b, double c) {
    double d; asm("fma.rn.f32x2 %0, %1, %2, %3;" : "=d"(d) : "d"(a), "d"(b), "d"(c)); return d;
}
__device__ __forceinline__ float2 unpack2(double p) {
    float2 f; asm("mov.b64 {%0,%1}, %2;" : "=f"(f.x), "=f"(f.y) : "d"(p)); return f;
}

__device__ __forceinline__ void cp16(void* smem, const void* g) {
    unsigned s = (unsigned)__cvta_generic_to_shared(smem);
    asm volatile("cp.async.ca.shared.global [%0], [%1], 16;\n" :: "r"(s), "l"(g));
}
__device__ __forceinline__ void cp_commit() { asm volatile("cp.async.commit_group;\n"); }
__device__ __forceinline__ void cp_wait0()  { asm volatile("cp.async.wait_group 0;\n"); }

// ---------------- init: z0 -> ZA (+ pads), b0 -> IB belief half, actions_0 ------
__global__ void init_kernel(const float* __restrict__ z0, const float* __restrict__ b0,
                            const float* __restrict__ actions0) {
    int i = blockIdx.x * blockDim.x + threadIdx.x;
    if (i < NB * 1024) {
        int r = i >> 10, c = i & 1023;
        g_ZA[r * ZA_LD + c] = z0[i];
        g_IB[r * 2048 + 1024 + c] = b0[i];
        if (c >= 1024 - 10) g_ZA[r * ZA_LD + (c + 16)] = 0.0f;  // cols 1030..1039
        if (c < NACT) g_ZA[r * ZA_LD + 1024 + c] = actions0[r * NACT + c];
    }
}

// ---------------- Wi1 zero-pad copy ----------------
__global__ void padw_kernel(const float* __restrict__ Wi1) {
    int i = blockIdx.x * blockDim.x + threadIdx.x;
    if (i < WI1_K * 1024) {
        int r = i >> 10;
        g_Wi1p[i] = (r < 1030) ? Wi1[i] : 0.0f;
    }
}

// ---------------- GEMM problem descriptor (two-region A for concat-free reads) --
struct GP {
    const float* A;   int lda;    // k in [0, ksplit)
    const float* A2;  int lda2;   // k in [ksplit, K)
    int ksplit;
    const float* W;   int ldw;
    const float* bias;
    float* C;         int ldc;
    int K;
};

// C = act(A @ W + bias). BM=BN=64, BK=16, **512 threads**, 2x4 microtile.
// A tile in smem as pre-duplicated doubles. Threads 0-255 load A, 256-511 load B
// (cp.async). Double-buffered, one __syncthreads per k-tile.
// blockIdx.z selects between two independent problems.
template <int DO_SILU>
__global__ void __launch_bounds__(512) gemm4_kernel(GP p0, GP p1) {
    GP p = blockIdx.z ? p1 : p0;
    __shared__ double As2[2][16][66];   // [buf][k][m] duplicated pairs (row 528B, 16B-mult)
    __shared__ float  Bs [2][16][64];   // [buf][k][n]

    const int tid = threadIdx.x;
    const int m0 = blockIdx.y * 64, n0 = blockIdx.x * 64;
    const bool isA = tid < 256;
    const int ar = tid & 63, ac = ((tid >> 6) & 3) << 2;  // A loader (tid<256)
    const int bt = tid & 255, br = bt >> 4, bc = (bt & 15) << 2;  // B loader (tid>=256)
    const int ty = tid >> 4, tx = tid & 15;               // output coords: rows ty*2+{0,1}, cols tx*4..

    const int ntiles = p.K >> 4;

    double acc[2][2];
    acc[0][0] = acc[0][1] = acc[1][0] = acc[1][1] = dup2(0.0f);

    // prologue: fill buffer 0
    if (isA) {
        const float* Ap = ((0 < p.ksplit) ? p.A + (size_t)(m0 + ar) * p.lda
                                          : p.A2 + (size_t)(m0 + ar) * p.lda2) + ac;
        float4 a = *(const float4*)Ap;
        As2[0][ac + 0][ar] = dup2(a.x); As2[0][ac + 1][ar] = dup2(a.y);
        As2[0][ac + 2][ar] = dup2(a.z); As2[0][ac + 3][ar] = dup2(a.w);
    } else {
        cp16(&Bs[0][br][bc], p.W + (size_t)br * p.ldw + n0 + bc);
        cp_commit();
        cp_wait0();
    }
    __syncthreads();

    for (int t = 0; t < ntiles; t++) {
        const int cur = t & 1, nxt = cur ^ 1;
        const bool more = (t + 1) < ntiles;
        float4 apf;
        if (more) {
            if (isA) {
                int kb = (t + 1) << 4;
                const float* Ap = (kb < p.ksplit)
                    ? p.A  + (size_t)(m0 + ar) * p.lda  + kb + ac
                    : p.A2 + (size_t)(m0 + ar) * p.lda2 + (kb - p.ksplit) + ac;
                apf = *(const float4*)Ap;
            } else {
                cp16(&Bs[nxt][br][bc], p.W + (size_t)((t + 1) * 16 + br) * p.ldw + n0 + bc);
                cp_commit();
            }
        }

#pragma unroll
        for (int kk = 0; kk < 16; kk++) {
            double2 a = *(const double2*)&As2[cur][kk][ty * 2];
            double2 b = *(const double2*)&Bs[cur][kk][tx * 4];
            acc[0][0] = ffma2(a.x, b.x, acc[0][0]); acc[0][1] = ffma2(a.x, b.y, acc[0][1]);
            acc[1][0] = ffma2(a.y, b.x, acc[1][0]); acc[1][1] = ffma2(a.y, b.y, acc[1][1]);
        }

        if (more) {
            if (isA) {
                As2[nxt][ac + 0][ar] = dup2(apf.x); As2[nxt][ac + 1][ar] = dup2(apf.y);
                As2[nxt][ac + 2][ar] = dup2(apf.z); As2[nxt][ac + 3][ar] = dup2(apf.w);
            } else {
                cp_wait0();
            }
        }
        __syncthreads();
    }

    // epilogue
#pragma unroll
    for (int i = 0; i < 2; i++) {
        const int m = m0 + ty * 2 + i;
        float* Crow = p.C + (size_t)m * p.ldc + n0 + tx * 4;
#pragma unroll
        for (int jp = 0; jp < 2; jp++) {
            float2 v = unpack2(acc[i][jp]);
            if (p.bias) {
                v.x += p.bias[n0 + tx * 4 + jp * 2 + 0];
                v.y += p.bias[n0 + tx * 4 + jp * 2 + 1];
            }
            if (DO_SILU) { v.x = silu_f(v.x); v.y = silu_f(v.y); }
            *(float2*)(Crow + jp * 2) = v;
        }
    }
}

// ---------------- LayerNorm(3072, eps=1e-3) + GRU update ----------------
__global__ void lngru_kernel(const float* __restrict__ ln_scale, const float* __restrict__ ln_bias) {
    const int row = blockIdx.x;
    const int tid = threadIdx.x;
    __shared__ float sh[8];
    __shared__ float bcast;

    const float* gr = g_G + (size_t)row * GDIM;
    float x[12];
    float s = 0.0f;
#pragma unroll
    for (int i = 0; i < 12; i++) { x[i] = gr[tid + i * 256]; s += x[i]; }

    s = warp_sum(s);
    if ((tid & 31) == 0) sh[tid >> 5] = s;
    __syncthreads();
    if (tid < 32) {
        float t = (tid < 8) ? sh[tid] : 0.0f;
        t = warp_sum(t);
        if (tid == 0) bcast = t;
    }
    __syncthreads();
    const float mu = __fdiv_rn(bcast, 3072.0f);
    __syncthreads();

    float v = 0.0f;
#pragma unroll
    for (int i = 0; i < 12; i++) { float d = x[i] - mu; v += d * d; }
    v = warp_sum(v);
    if ((tid & 31) == 0) sh[tid >> 5] = v;
    __syncthreads();
    if (tid < 32) {
        float t = (tid < 8) ? sh[tid] : 0.0f;
        t = warp_sum(t);
        if (tid == 0) bcast = t;
    }
    __syncthreads();
    const float var = __fdiv_rn(bcast, 3072.0f);
    const float denom = __fsqrt_rn(var + 1e-3f);

#pragma unroll
    for (int jj = 0; jj < 4; jj++) {
        int j = tid + jj * 256;
        float yr = __fdiv_rn(x[jj]     - mu, denom) * ln_scale[j]        + ln_bias[j];
        float yc = __fdiv_rn(x[jj + 4] - mu, denom) * ln_scale[j + 1024] + ln_bias[j + 1024];
        float yu = __fdiv_rn(x[jj + 8] - mu, denom) * ln_scale[j + 2048] + ln_bias[j + 2048];
        float reset = sigmoid_f(yr);
        float cand  = (float)tanh((double)(reset * yc));
        float upd   = sigmoid_f(yu - 1.0f);   // UPDATE_BIAS = -1
        float bprev = g_IB[(size_t)row * 2048 + 1024 + j];
        float bn = upd * cand + (1.0f - upd) * bprev;
        g_IB[(size_t)row * 2048 + 1024 + j] = bn;
    }
}

// ---------------- softmax/unimix/KL + gumbel-max sample; also stages next actions
__global__ void sample_kernel(const float* __restrict__ U_t, float* __restrict__ losses_t,
                              const float* __restrict__ actions_next) {
    const int row = blockIdx.x;
    const int tid = threadIdx.x;
    const int warp = tid >> 5, lane = tid & 31;
    __shared__ float klsh[8];

    if (actions_next && tid < NACT)
        g_ZA[(size_t)row * ZA_LD + 1024 + tid] = actions_next[row * NACT + tid];

    float klacc = 0.0f;
#pragma unroll
    for (int sg = 0; sg < 4; sg++) {
        const int s2 = warp * 4 + sg;
        const int idx = row * 1024 + s2 * 32 + lane;

        float pl = fminf(fmaxf(g_PL[idx], -20.0f), 20.0f);
        float ql = fminf(fmaxf(g_QL[idx], -20.0f), 20.0f);

        float pm = warp_max(pl);
        float pe = (float)exp((double)(pl - pm));
        float ps = warp_sum(pe);
        float pp = __fdiv_rn(pe, ps) * 0.99f + (0.01f / 32.0f);

        float qm = warp_max(ql);
        float qe = (float)exp((double)(ql - qm));
        float qs = warp_sum(qe);
        float qp = __fdiv_rn(qe, qs) * 0.99f + (0.01f / 32.0f);

        klacc += qp * (float)(log((double)(qp + 1e-8f)) - log((double)(pp + 1e-8f)));

        float u = U_t[row * 1024 + s2 * 32 + lane];
        float gum = (float)(-log(-log((double)u + 1e-6) + 1e-6));
        float val = (float)log((double)fmaxf(qp, 1e-6f)) + gum;
        float bv = val; int bi = lane;
#pragma unroll
        for (int o = 16; o; o >>= 1) {
            float ov = __shfl_xor_sync(0xffffffffu, bv, o);
            int   oi = __shfl_xor_sync(0xffffffffu, bi, o);
            if (ov > bv || (ov == bv && oi < bi)) { bv = ov; bi = oi; }
        }
        float y = (lane == bi) ? 1.0f : 0.0f;
        float z = __fsub_rn(__fadd_rn(y, qp), qp);
        g_ZA[(size_t)row * ZA_LD + s2 * 32 + lane] = z;
    }

    float w = warp_sum(klacc);
    if (lane == 0) klsh[warp] = w;
    __syncthreads();
    if (tid == 0) {
        float kl = 0.0f;
#pragma unroll
        for (int i = 0; i < 8; i++) kl += klsh[i];
        float m = fmaxf(kl, 0.1f);
        losses_t[row] = 1.0f * m + 0.1f * m;
    }
}

// ---------------- launch ----------------
extern "C" void kernel_launch(void* const* d_in, const int* in_sizes, int n_in,
                              void* d_out, int out_size) {
    const float* b0       = (const float*)d_in[0];
    const float* z0       = (const float*)d_in[1];
    const float* actions  = (const float*)d_in[2];
    const float* obs      = (const float*)d_in[3];
    const float* u_noise  = (const float*)d_in[4];
    const float* Wi1      = (const float*)d_in[5];
    const float* bi1      = (const float*)d_in[6];
    const float* Wi2      = (const float*)d_in[7];
    const float* bi2      = (const float*)d_in[8];
    const float* Wg       = (const float*)d_in[9];
    const float* ln_scale = (const float*)d_in[10];
    const float* ln_bias  = (const float*)d_in[11];
    const float* Wo1      = (const float*)d_in[12];
    const float* bo1      = (const float*)d_in[13];
    const float* Wo2      = (const float*)d_in[14];
    const float* bo2      = (const float*)d_in[15];
    const float* Wp1      = (const float*)d_in[16];
    const float* bp1      = (const float*)d_in[17];
    const float* Wp2      = (const float*)d_in[18];
    const float* bp2      = (const float*)d_in[19];
    float* out = (float*)d_out;

    float *pZA, *pH1, *pIB, *pG, *pHP, *pHO, *pPL, *pQL, *pWi1p;
    cudaGetSymbolAddress((void**)&pZA, g_ZA);
    cudaGetSymbolAddress((void**)&pH1, g_H1);
    cudaGetSymbolAddress((void**)&pIB, g_IB);
    cudaGetSymbolAddress((void**)&pG,  g_G);
    cudaGetSymbolAddress((void**)&pHP, g_HP);
    cudaGetSymbolAddress((void**)&pHO, g_HO);
    cudaGetSymbolAddress((void**)&pPL, g_PL);
    cudaGetSymbolAddress((void**)&pQL, g_QL);
    cudaGetSymbolAddress((void**)&pWi1p, g_Wi1p);

    init_kernel<<<(NB * 1024 + 255) / 256, 256>>>(z0, b0, actions);
    padw_kernel<<<(WI1_K * 1024 + 255) / 256, 256>>>(Wi1);

    const dim3 g1(16, 4, 1);     // single N=1024 GEMM
    const dim3 g1p(16, 4, 2);    // paired N=1024 GEMMs
    const dim3 gg(48, 4, 1);     // GRU gate GEMM (N=3072)

    const float* belief = pIB + 1024;

    for (int t = 0; t < NT; t++) {
        const float* obs_t = obs + (size_t)t * NB * 1024;

        // imagine MLP
        GP i1{pZA, ZA_LD, pZA, ZA_LD, WI1_K, pWi1p, 1024, bi1, pH1, 1024, WI1_K};
        gemm4_kernel<1><<<g1, 512>>>(i1, i1);
        GP i2{pH1, 1024, pH1, 1024, 1024, Wi2, 1024, bi2, pIB, 2048, 1024};
        gemm4_kernel<0><<<g1, 512>>>(i2, i2);

        // GRU gates + LN/GRU update
        GP ggp{pIB, 2048, pIB, 2048, 2048, Wg, 3072, nullptr, pG, 3072, 2048};
        gemm4_kernel<0><<<gg, 512>>>(ggp, ggp);
        lngru_kernel<<<NB, 256>>>(ln_scale, ln_bias);

        // prior layer1 || posterior layer1 (both SiLU); o1 A = [obs_t | belief]
        GP p1{belief, 2048, belief, 2048, 1024, Wp1, 1024, bp1, pHP, 1024, 1024};
        GP o1{obs_t,  1024, belief, 2048, 1024, Wo1, 1024, bo1, pHO, 1024, 2048};
        gemm4_kernel<1><<<g1p, 512>>>(p1, o1);

        // prior layer2 || posterior layer2
        GP p2{pHP, 1024, pHP, 1024, 1024, Wp2, 1024, bp2, pPL, 1024, 1024};
        GP o2{pHO, 1024, pHO, 1024, 1024, Wo2, 1024, bo2, pQL, 1024, 1024};
        gemm4_kernel<0><<<g1p, 512>>>(p2, o2);

        // probs + KL + gumbel sample (+ stage next step's actions)
        const float* an = (t + 1 < NT) ? (actions + (size_t)(t + 1) * NB * NACT) : nullptr;
        sample_kernel<<<NB, 256>>>(u_noise + (size_t)t * NB * 1024, out + (size_t)t * NB, an);
    }
}

// round 6
// speedup vs baseline: 1.2790x; 1.2790x over previous
#include <cuda_runtime.h>
#include <math.h>

#define NB 256        // batch
#define NT 64         // timesteps
#define NACT 6
#define GDIM 3072
#define ZA_LD 1040    // 1024 z + 6 act + 10 zero pad (K=1040 multiple of 16)
#define WI1_K 1040

// ---------------- scratch (device globals: no allocation allowed) ----------------
__device__ float g_ZA[NB * ZA_LD];       // [z (1024) | action (6) | zero pad]
__device__ float g_H1[NB * 1024];        // imagine hidden
__device__ float g_IB[NB * 2048];        // [inp (1024) | belief (1024)]
__device__ float g_G [NB * GDIM];        // raw GRU gates
__device__ float g_HP[NB * 1024];        // prior hidden
__device__ float g_HO[NB * 1024];        // post hidden
__device__ float g_PL[NB * 1024];        // prior logits
__device__ float g_QL[NB * 1024];        // post logits
__device__ float g_Wi1p[WI1_K * 1024];   // Wi1 zero-padded to K=1040 rows

// ---------------- helpers ----------------
__device__ __forceinline__ float warp_sum(float v) {
#pragma unroll
    for (int o = 16; o; o >>= 1) v += __shfl_xor_sync(0xffffffffu, v, o);
    return v;
}
__device__ __forceinline__ float warp_max(float v) {
#pragma unroll
    for (int o = 16; o; o >>= 1) v = fmaxf(v, __shfl_xor_sync(0xffffffffu, v, o));
    return v;
}

// precise transcendentals via double path (immune to --use_fast_math rewrites)
__device__ __forceinline__ float silu_f(float x) {
    double e = exp(-(double)x);
    return (float)((double)x / (1.0 + e));
}
__device__ __forceinline__ float sigmoid_f(float x) {
    return (float)(1.0 / (1.0 + exp(-(double)x)));
}

__device__ __forceinline__ void cp16(void* smem, const void* g) {
    unsigned s = (unsigned)__cvta_generic_to_shared(smem);
    asm volatile("cp.async.ca.shared.global [%0], [%1], 16;\n" :: "r"(s), "l"(g));
}
__device__ __forceinline__ void cp_commit() { asm volatile("cp.async.commit_group;\n"); }
__device__ __forceinline__ void cp_wait0()  { asm volatile("cp.async.wait_group 0;\n"); }

// ---------------- init: z0 -> ZA (+ pads), b0 -> IB belief half, actions_0 ------
__global__ void init_kernel(const float* __restrict__ z0, const float* __restrict__ b0,
                            const float* __restrict__ actions0) {
    int i = blockIdx.x * blockDim.x + threadIdx.x;
    if (i < NB * 1024) {
        int r = i >> 10, c = i & 1023;
        g_ZA[r * ZA_LD + c] = z0[i];
        g_IB[r * 2048 + 1024 + c] = b0[i];
        if (c >= 1024 - 10) g_ZA[r * ZA_LD + (c + 16)] = 0.0f;  // cols 1030..1039
        if (c < NACT) g_ZA[r * ZA_LD + 1024 + c] = actions0[r * NACT + c];
    }
}

// ---------------- Wi1 zero-pad copy ----------------
__global__ void padw_kernel(const float* __restrict__ Wi1) {
    int i = blockIdx.x * blockDim.x + threadIdx.x;
    if (i < WI1_K * 1024) {
        int r = i >> 10;
        g_Wi1p[i] = (r < 1030) ? Wi1[i] : 0.0f;
    }
}

// ---------------- GEMM problem descriptor (two-region A for concat-free reads) --
struct GP {
    const float* A;   int lda;    // k in [0, ksplit)
    const float* A2;  int lda2;   // k in [ksplit, K)
    int ksplit;
    const float* W;   int ldw;
    const float* bias;
    float* C;         int ldc;
    int K;
};

// C = act(A @ W + bias). BM=64, BN=32, BK=16, 256 threads, 4x2 microtile, plain
// FFMA (bit-exact ascending-k chain per output). Double-buffered smem, cp.async
// for the W tile (threads 0-127), one __syncthreads per k-tile.
// blockIdx.z selects between two independent problems.
template <int DO_SILU>
__global__ void __launch_bounds__(256) gemm5_kernel(GP p0, GP p1) {
    GP p = blockIdx.z ? p1 : p0;
    __shared__ float As[2][16][64];   // [buf][k][m]
    __shared__ float Bs[2][16][32];   // [buf][k][n]

    const int tid = threadIdx.x;
    const int m0 = blockIdx.y * 64, n0 = blockIdx.x * 32;
    const int ar = tid & 63, ac = (tid >> 6) << 2;        // A loader: row ar, k ac..ac+3
    const int br = tid >> 3, bc = (tid & 7) << 2;         // B loader (tid<128): k-row br, n bc..bc+3
    const int ty = tid >> 4, tx = tid & 15;               // out: rows ty*4+i, cols tx*2+j

    const int ntiles = p.K >> 4;

    // per-tile A source pointer (region split at ksplit; ksplit % 16 == 0)
    auto aptr = [&](int t) -> const float* {
        int kb = t << 4;
        return (kb < p.ksplit)
            ? p.A  + (size_t)(m0 + ar) * p.lda  + kb + ac
            : p.A2 + (size_t)(m0 + ar) * p.lda2 + (kb - p.ksplit) + ac;
    };

    float acc[4][2] = {};

    // prologue: fill buffer 0
    {
        float4 a = *(const float4*)aptr(0);
        if (tid < 128) cp16(&Bs[0][br][bc], p.W + (size_t)br * p.ldw + n0 + bc);
        cp_commit();
        As[0][ac + 0][ar] = a.x; As[0][ac + 1][ar] = a.y;
        As[0][ac + 2][ar] = a.z; As[0][ac + 3][ar] = a.w;
        cp_wait0();
    }
    __syncthreads();

    for (int t = 0; t < ntiles; t++) {
        const int cur = t & 1, nxt = cur ^ 1;
        const bool more = (t + 1) < ntiles;
        float4 apf;
        if (more) {
            apf = *(const float4*)aptr(t + 1);
            if (tid < 128)
                cp16(&Bs[nxt][br][bc], p.W + (size_t)((t + 1) * 16 + br) * p.ldw + n0 + bc);
            cp_commit();
        }

#pragma unroll
        for (int kk = 0; kk < 16; kk++) {
            float4 a = *(const float4*)&As[cur][kk][ty * 4];
            float2 b = *(const float2*)&Bs[cur][kk][tx * 2];
            acc[0][0] += a.x * b.x; acc[0][1] += a.x * b.y;
            acc[1][0] += a.y * b.x; acc[1][1] += a.y * b.y;
            acc[2][0] += a.z * b.x; acc[2][1] += a.z * b.y;
            acc[3][0] += a.w * b.x; acc[3][1] += a.w * b.y;
        }

        if (more) {
            As[nxt][ac + 0][ar] = apf.x; As[nxt][ac + 1][ar] = apf.y;
            As[nxt][ac + 2][ar] = apf.z; As[nxt][ac + 3][ar] = apf.w;
            cp_wait0();
        }
        __syncthreads();
    }

    // epilogue
#pragma unroll
    for (int i = 0; i < 4; i++) {
        const int m = m0 + ty * 4 + i;
        float2 v = make_float2(acc[i][0], acc[i][1]);
        if (p.bias) {
            v.x += p.bias[n0 + tx * 2 + 0];
            v.y += p.bias[n0 + tx * 2 + 1];
        }
        if (DO_SILU) { v.x = silu_f(v.x); v.y = silu_f(v.y); }
        *(float2*)(p.C + (size_t)m * p.ldc + n0 + tx * 2) = v;
    }
}

// ---------------- LayerNorm(3072, eps=1e-3) + GRU update ----------------
__global__ void lngru_kernel(const float* __restrict__ ln_scale, const float* __restrict__ ln_bias) {
    const int row = blockIdx.x;
    const int tid = threadIdx.x;
    __shared__ float sh[8];
    __shared__ float bcast;

    const float* gr = g_G + (size_t)row * GDIM;
    float x[12];
    float s = 0.0f;
#pragma unroll
    for (int i = 0; i < 12; i++) { x[i] = gr[tid + i * 256]; s += x[i]; }

    s = warp_sum(s);
    if ((tid & 31) == 0) sh[tid >> 5] = s;
    __syncthreads();
    if (tid < 32) {
        float t = (tid < 8) ? sh[tid] : 0.0f;
        t = warp_sum(t);
        if (tid == 0) bcast = t;
    }
    __syncthreads();
    const float mu = __fdiv_rn(bcast, 3072.0f);
    __syncthreads();

    float v = 0.0f;
#pragma unroll
    for (int i = 0; i < 12; i++) { float d = x[i] - mu; v += d * d; }
    v = warp_sum(v);
    if ((tid & 31) == 0) sh[tid >> 5] = v;
    __syncthreads();
    if (tid < 32) {
        float t = (tid < 8) ? sh[tid] : 0.0f;
        t = warp_sum(t);
        if (tid == 0) bcast = t;
    }
    __syncthreads();
    const float var = __fdiv_rn(bcast, 3072.0f);
    const float denom = __fsqrt_rn(var + 1e-3f);

#pragma unroll
    for (int jj = 0; jj < 4; jj++) {
        int j = tid + jj * 256;
        float yr = __fdiv_rn(x[jj]     - mu, denom) * ln_scale[j]        + ln_bias[j];
        float yc = __fdiv_rn(x[jj + 4] - mu, denom) * ln_scale[j + 1024] + ln_bias[j + 1024];
        float yu = __fdiv_rn(x[jj + 8] - mu, denom) * ln_scale[j + 2048] + ln_bias[j + 2048];
        float reset = sigmoid_f(yr);
        float cand  = (float)tanh((double)(reset * yc));
        float upd   = sigmoid_f(yu - 1.0f);   // UPDATE_BIAS = -1
        float bprev = g_IB[(size_t)row * 2048 + 1024 + j];
        float bn = upd * cand + (1.0f - upd) * bprev;
        g_IB[(size_t)row * 2048 + 1024 + j] = bn;
    }
}

// ---------------- softmax/unimix/KL + gumbel-max sample; also stages next actions
__global__ void sample_kernel(const float* __restrict__ U_t, float* __restrict__ losses_t,
                              const float* __restrict__ actions_next) {
    const int row = blockIdx.x;
    const int tid = threadIdx.x;
    const int warp = tid >> 5, lane = tid & 31;
    __shared__ float klsh[8];

    if (actions_next && tid < NACT)
        g_ZA[(size_t)row * ZA_LD + 1024 + tid] = actions_next[row * NACT + tid];

    float klacc = 0.0f;
#pragma unroll
    for (int sg = 0; sg < 4; sg++) {
        const int s2 = warp * 4 + sg;
        const int idx = row * 1024 + s2 * 32 + lane;

        float pl = fminf(fmaxf(g_PL[idx], -20.0f), 20.0f);
        float ql = fminf(fmaxf(g_QL[idx], -20.0f), 20.0f);

        float pm = warp_max(pl);
        float pe = (float)exp((double)(pl - pm));
        float ps = warp_sum(pe);
        float pp = __fdiv_rn(pe, ps) * 0.99f + (0.01f / 32.0f);

        float qm = warp_max(ql);
        float qe = (float)exp((double)(ql - qm));
        float qs = warp_sum(qe);
        float qp = __fdiv_rn(qe, qs) * 0.99f + (0.01f / 32.0f);

        klacc += qp * (float)(log((double)(qp + 1e-8f)) - log((double)(pp + 1e-8f)));

        float u = U_t[row * 1024 + s2 * 32 + lane];
        float gum = (float)(-log(-log((double)u + 1e-6) + 1e-6));
        float val = (float)log((double)fmaxf(qp, 1e-6f)) + gum;
        float bv = val; int bi = lane;
#pragma unroll
        for (int o = 16; o; o >>= 1) {
            float ov = __shfl_xor_sync(0xffffffffu, bv, o);
            int   oi = __shfl_xor_sync(0xffffffffu, bi, o);
            if (ov > bv || (ov == bv && oi < bi)) { bv = ov; bi = oi; }
        }
        float y = (lane == bi) ? 1.0f : 0.0f;
        float z = __fsub_rn(__fadd_rn(y, qp), qp);
        g_ZA[(size_t)row * ZA_LD + s2 * 32 + lane] = z;
    }

    float w = warp_sum(klacc);
    if (lane == 0) klsh[warp] = w;
    __syncthreads();
    if (tid == 0) {
        float kl = 0.0f;
#pragma unroll
        for (int i = 0; i < 8; i++) kl += klsh[i];
        float m = fmaxf(kl, 0.1f);
        losses_t[row] = 1.0f * m + 0.1f * m;
    }
}

// ---------------- launch ----------------
extern "C" void kernel_launch(void* const* d_in, const int* in_sizes, int n_in,
                              void* d_out, int out_size) {
    const float* b0       = (const float*)d_in[0];
    const float* z0       = (const float*)d_in[1];
    const float* actions  = (const float*)d_in[2];
    const float* obs      = (const float*)d_in[3];
    const float* u_noise  = (const float*)d_in[4];
    const float* Wi1      = (const float*)d_in[5];
    const float* bi1      = (const float*)d_in[6];
    const float* Wi2      = (const float*)d_in[7];
    const float* bi2      = (const float*)d_in[8];
    const float* Wg       = (const float*)d_in[9];
    const float* ln_scale = (const float*)d_in[10];
    const float* ln_bias  = (const float*)d_in[11];
    const float* Wo1      = (const float*)d_in[12];
    const float* bo1      = (const float*)d_in[13];
    const float* Wo2      = (const float*)d_in[14];
    const float* bo2      = (const float*)d_in[15];
    const float* Wp1      = (const float*)d_in[16];
    const float* bp1      = (const float*)d_in[17];
    const float* Wp2      = (const float*)d_in[18];
    const float* bp2      = (const float*)d_in[19];
    float* out = (float*)d_out;

    float *pZA, *pH1, *pIB, *pG, *pHP, *pHO, *pPL, *pQL, *pWi1p;
    cudaGetSymbolAddress((void**)&pZA, g_ZA);
    cudaGetSymbolAddress((void**)&pH1, g_H1);
    cudaGetSymbolAddress((void**)&pIB, g_IB);
    cudaGetSymbolAddress((void**)&pG,  g_G);
    cudaGetSymbolAddress((void**)&pHP, g_HP);
    cudaGetSymbolAddress((void**)&pHO, g_HO);
    cudaGetSymbolAddress((void**)&pPL, g_PL);
    cudaGetSymbolAddress((void**)&pQL, g_QL);
    cudaGetSymbolAddress((void**)&pWi1p, g_Wi1p);

    init_kernel<<<(NB * 1024 + 255) / 256, 256>>>(z0, b0, actions);
    padw_kernel<<<(WI1_K * 1024 + 255) / 256, 256>>>(Wi1);

    const dim3 g1(32, 4, 1);     // single N=1024 GEMM: 128 blocks
    const dim3 g1p(32, 4, 2);    // paired N=1024 GEMMs: 256 blocks
    const dim3 gg(96, 4, 1);     // GRU gate GEMM (N=3072): 384 blocks

    const float* belief = pIB + 1024;

    for (int t = 0; t < NT; t++) {
        const float* obs_t = obs + (size_t)t * NB * 1024;

        // imagine MLP
        GP i1{pZA, ZA_LD, pZA, ZA_LD, WI1_K, pWi1p, 1024, bi1, pH1, 1024, WI1_K};
        gemm5_kernel<1><<<g1, 256>>>(i1, i1);
        GP i2{pH1, 1024, pH1, 1024, 1024, Wi2, 1024, bi2, pIB, 2048, 1024};
        gemm5_kernel<0><<<g1, 256>>>(i2, i2);

        // GRU gates + LN/GRU update
        GP ggp{pIB, 2048, pIB, 2048, 2048, Wg, 3072, nullptr, pG, 3072, 2048};
        gemm5_kernel<0><<<gg, 256>>>(ggp, ggp);
        lngru_kernel<<<NB, 256>>>(ln_scale, ln_bias);

        // prior layer1 || posterior layer1 (both SiLU); o1 A = [obs_t | belief]
        GP p1{belief, 2048, belief, 2048, 1024, Wp1, 1024, bp1, pHP, 1024, 1024};
        GP o1{obs_t,  1024, belief, 2048, 1024, Wo1, 1024, bo1, pHO, 1024, 2048};
        gemm5_kernel<1><<<g1p, 256>>>(p1, o1);

        // prior layer2 || posterior layer2
        GP p2{pHP, 1024, pHP, 1024, 1024, Wp2, 1024, bp2, pPL, 1024, 1024};
        GP o2{pHO, 1024, pHO, 1024, 1024, Wo2, 1024, bo2, pQL, 1024, 1024};
        gemm5_kernel<0><<<g1p, 256>>>(p2, o2);

        // probs + KL + gumbel sample (+ stage next step's actions)
        const float* an = (t + 1 < NT) ? (actions + (size_t)(t + 1) * NB * NACT) : nullptr;
        sample_kernel<<<NB, 256>>>(u_noise + (size_t)t * NB * 1024, out + (size_t)t * NB, an);
    }
}

// round 8
// speedup vs baseline: 1.6465x; 1.2874x over previous
#include <cuda_runtime.h>
#include <math.h>

#define NB 256        // batch
#define NT 64         // timesteps
#define NACT 6
#define GDIM 3072
#define ZA_LD 1040    // 1024 z + 6 act + 10 zero pad (K=1040 multiple of 16)
#define WI1_K 1040

// ---------------- scratch (device globals: no allocation allowed) ----------------
__device__ float g_ZA[NB * ZA_LD];        // [z (1024) | action (6) | zero pad]
__device__ float g_H1[NB * 1024];         // imagine hidden (post-silu)
__device__ float g_IB[NB * 2048];         // [inp (1024) | belief (1024)]
__device__ float g_HP[NB * 1024];         // prior hidden (post-silu)
__device__ float g_HO[NB * 1024];         // post hidden (post-silu)
__device__ float g_PP[4][NB * 1024];      // split-K partial pool (reused per phase)
__device__ float g_GG[2][NB * GDIM];      // gg GEMM partials
__device__ float g_Wi1p[WI1_K * 1024];    // Wi1 zero-padded to K=1040 rows

// ---------------- helpers ----------------
__device__ __forceinline__ float warp_sum(float v) {
#pragma unroll
    for (int o = 16; o; o >>= 1) v += __shfl_xor_sync(0xffffffffu, v, o);
    return v;
}
__device__ __forceinline__ float warp_max(float v) {
#pragma unroll
    for (int o = 16; o; o >>= 1) v = fmaxf(v, __shfl_xor_sync(0xffffffffu, v, o));
    return v;
}
__device__ __forceinline__ float silu_f(float x) {
    double e = exp(-(double)x);
    return (float)((double)x / (1.0 + e));
}
__device__ __forceinline__ float sigmoid_f(float x) {
    return (float)(1.0 / (1.0 + exp(-(double)x)));
}

__device__ __forceinline__ void cp16(void* smem, const void* g) {
    unsigned s = (unsigned)__cvta_generic_to_shared(smem);
    asm volatile("cp.async.ca.shared.global [%0], [%1], 16;\n" :: "r"(s), "l"(g));
}
__device__ __forceinline__ void cp_commit() { asm volatile("cp.async.commit_group;\n"); }
__device__ __forceinline__ void cp_wait0()  { asm volatile("cp.async.wait_group 0;\n"); }

// ---------------- init ----------------
__global__ void init_kernel(const float* __restrict__ z0, const float* __restrict__ b0,
                            const float* __restrict__ actions0) {
    int i = blockIdx.x * blockDim.x + threadIdx.x;
    if (i < NB * 1024) {
        int r = i >> 10, c = i & 1023;
        g_ZA[r * ZA_LD + c] = z0[i];
        g_IB[r * 2048 + 1024 + c] = b0[i];
        if (c >= 1024 - 10) g_ZA[r * ZA_LD + (c + 16)] = 0.0f;  // cols 1030..1039
        if (c < NACT) g_ZA[r * ZA_LD + 1024 + c] = actions0[r * NACT + c];
    }
}
__global__ void padw_kernel(const float* __restrict__ Wi1) {
    int i = blockIdx.x * blockDim.x + threadIdx.x;
    if (i < WI1_K * 1024) {
        int r = i >> 10;
        g_Wi1p[i] = (r < 1030) ? Wi1[i] : 0.0f;
    }
}

// ---------------- GEMM: pure partial product C = A[k0:k1] @ W[k0:k1] ------------
struct GP {
    const float* A;   int lda;    // k in [0, ksplit)
    const float* A2;  int lda2;   // k in [ksplit, K)
    int ksplit;
    const float* W;   int ldw;
    float* C;         int ldc;
    int k0, k1;                   // k-range (multiples of 16)
};

// BM=BN=64, BK=16, 256 threads, 4x4 microtile, double-buffered, cp.async for W.
// blockIdx.z selects one of four problem descriptors (split-K slices / pairs).
__global__ void __launch_bounds__(256) gemm7_kernel(GP p0, GP p1, GP p2, GP p3) {
    GP p = (blockIdx.z == 0) ? p0 : (blockIdx.z == 1) ? p1 : (blockIdx.z == 2) ? p2 : p3;
    __shared__ float As[2][16][64];
    __shared__ float Bs[2][16][64];

    const int tid = threadIdx.x;
    const int m0 = blockIdx.y * 64, n0 = blockIdx.x * 64;
    const int ar = tid & 63, ac = (tid >> 6) << 2;     // A loader: row ar, k-cols ac..ac+3
    const int br = tid >> 4, bc = (tid & 15) << 2;     // W loader: k-row br, n-cols bc..bc+3
    const int ty = tid >> 4, tx = tid & 15;

    const int t0 = p.k0 >> 4, tN = p.k1 >> 4;

    auto aptr = [&](int t) -> const float* {
        int kb = t << 4;
        return (kb < p.ksplit)
            ? p.A  + (size_t)(m0 + ar) * p.lda  + kb + ac
            : p.A2 + (size_t)(m0 + ar) * p.lda2 + (kb - p.ksplit) + ac;
    };

    float acc[4][4] = {};

    // prologue: fill buffer 0
    {
        float4 a = *(const float4*)aptr(t0);
        cp16(&Bs[0][br][bc], p.W + (size_t)(p.k0 + br) * p.ldw + n0 + bc);
        cp_commit();
        As[0][ac + 0][ar] = a.x; As[0][ac + 1][ar] = a.y;
        As[0][ac + 2][ar] = a.z; As[0][ac + 3][ar] = a.w;
        cp_wait0();
    }
    __syncthreads();

    for (int t = t0; t < tN; t++) {
        const int cur = (t - t0) & 1, nxt = cur ^ 1;
        const bool more = (t + 1) < tN;
        float4 apf;
        if (more) {
            apf = *(const float4*)aptr(t + 1);
            cp16(&Bs[nxt][br][bc], p.W + (size_t)((t + 1) * 16 + br) * p.ldw + n0 + bc);
            cp_commit();
        }
#pragma unroll
        for (int kk = 0; kk < 16; kk++) {
            float4 a = *(const float4*)&As[cur][kk][ty * 4];
            float4 b = *(const float4*)&Bs[cur][kk][tx * 4];
            acc[0][0] += a.x * b.x; acc[0][1] += a.x * b.y; acc[0][2] += a.x * b.z; acc[0][3] += a.x * b.w;
            acc[1][0] += a.y * b.x; acc[1][1] += a.y * b.y; acc[1][2] += a.y * b.z; acc[1][3] += a.y * b.w;
            acc[2][0] += a.z * b.x; acc[2][1] += a.z * b.y; acc[2][2] += a.z * b.z; acc[2][3] += a.z * b.w;
            acc[3][0] += a.w * b.x; acc[3][1] += a.w * b.y; acc[3][2] += a.w * b.z; acc[3][3] += a.w * b.w;
        }
        if (more) {
            As[nxt][ac + 0][ar] = apf.x; As[nxt][ac + 1][ar] = apf.y;
            As[nxt][ac + 2][ar] = apf.z; As[nxt][ac + 3][ar] = apf.w;
            cp_wait0();
        }
        __syncthreads();
    }

#pragma unroll
    for (int i = 0; i < 4; i++) {
        const int m = m0 + ty * 4 + i;
        *(float4*)(p.C + (size_t)m * p.ldc + n0 + tx * 4) = *(float4*)&acc[i][0];
    }
}

// ---------------- fuse: out = [silu](PP0+PP1+PP2+PP3 + bias), N=1024 cols --------
// grid: 256 blocks x 256 threads, each thread one float4 -> 262144 floats total
__global__ void fuse4_kernel(const float* __restrict__ bias, float* __restrict__ out,
                             int ldo, int dsilu) {
    int i = (blockIdx.x * blockDim.x + threadIdx.x) << 2;
    int r = i >> 10, c = i & 1023;
    float4 v0 = *(const float4*)&g_PP[0][i];
    float4 v1 = *(const float4*)&g_PP[1][i];
    float4 v2 = *(const float4*)&g_PP[2][i];
    float4 v3 = *(const float4*)&g_PP[3][i];
    float4 b4 = *(const float4*)&bias[c];
    float4 o;
    o.x = ((v0.x + v1.x) + (v2.x + v3.x)) + b4.x;
    o.y = ((v0.y + v1.y) + (v2.y + v3.y)) + b4.y;
    o.z = ((v0.z + v1.z) + (v2.z + v3.z)) + b4.z;
    o.w = ((v0.w + v1.w) + (v2.w + v3.w)) + b4.w;
    if (dsilu) { o.x = silu_f(o.x); o.y = silu_f(o.y); o.z = silu_f(o.z); o.w = silu_f(o.w); }
    *(float4*)(out + (size_t)r * ldo + c) = o;
}

// ---------------- fuse22: HP = silu(PP0+PP1+bp1), HO = silu(PP2+PP3+bo1) ---------
__global__ void fuse22_kernel(const float* __restrict__ bp1, const float* __restrict__ bo1) {
    int i = (blockIdx.x * blockDim.x + threadIdx.x) << 2;
    int c = i & 1023;
    const float* P0 = g_PP[blockIdx.y * 2 + 0];
    const float* P1 = g_PP[blockIdx.y * 2 + 1];
    const float* bias = blockIdx.y ? bo1 : bp1;
    float* out = blockIdx.y ? g_HO : g_HP;
    float4 v0 = *(const float4*)&P0[i];
    float4 v1 = *(const float4*)&P1[i];
    float4 b4 = *(const float4*)&bias[c];
    float4 o;
    o.x = silu_f(v0.x + v1.x + b4.x);
    o.y = silu_f(v0.y + v1.y + b4.y);
    o.z = silu_f(v0.z + v1.z + b4.z);
    o.w = silu_f(v0.w + v1.w + b4.w);
    *(float4*)(out + i) = o;
}

// ---------------- LayerNorm(3072, eps=1e-3) + GRU update (sums GG partials) ------
__global__ void lngru_kernel(const float* __restrict__ ln_scale, const float* __restrict__ ln_bias) {
    const int row = blockIdx.x;
    const int tid = threadIdx.x;
    __shared__ float sh[8];
    __shared__ float bcast;

    const float* g0 = g_GG[0] + (size_t)row * GDIM;
    const float* g1 = g_GG[1] + (size_t)row * GDIM;
    float x[12];
    float s = 0.0f;
#pragma unroll
    for (int i = 0; i < 12; i++) {
        x[i] = g0[tid + i * 256] + g1[tid + i * 256];
        s += x[i];
    }

    s = warp_sum(s);
    if ((tid & 31) == 0) sh[tid >> 5] = s;
    __syncthreads();
    if (tid < 32) {
        float t = (tid < 8) ? sh[tid] : 0.0f;
        t = warp_sum(t);
        if (tid == 0) bcast = t;
    }
    __syncthreads();
    const float mu = __fdiv_rn(bcast, 3072.0f);
    __syncthreads();

    float v = 0.0f;
#pragma unroll
    for (int i = 0; i < 12; i++) { float d = x[i] - mu; v += d * d; }
    v = warp_sum(v);
    if ((tid & 31) == 0) sh[tid >> 5] = v;
    __syncthreads();
    if (tid < 32) {
        float t = (tid < 8) ? sh[tid] : 0.0f;
        t = warp_sum(t);
        if (tid == 0) bcast = t;
    }
    __syncthreads();
    const float var = __fdiv_rn(bcast, 3072.0f);
    const float denom = __fsqrt_rn(var + 1e-3f);

#pragma unroll
    for (int jj = 0; jj < 4; jj++) {
        int j = tid + jj * 256;
        float yr = __fdiv_rn(x[jj]     - mu, denom) * ln_scale[j]        + ln_bias[j];
        float yc = __fdiv_rn(x[jj + 4] - mu, denom) * ln_scale[j + 1024] + ln_bias[j + 1024];
        float yu = __fdiv_rn(x[jj + 8] - mu, denom) * ln_scale[j + 2048] + ln_bias[j + 2048];
        float reset = sigmoid_f(yr);
        float cand  = (float)tanh((double)(reset * yc));
        float upd   = sigmoid_f(yu - 1.0f);   // UPDATE_BIAS = -1
        float bprev = g_IB[(size_t)row * 2048 + 1024 + j];
        float bn = upd * cand + (1.0f - upd) * bprev;
        g_IB[(size_t)row * 2048 + 1024 + j] = bn;
    }
}

// ---------------- softmax/unimix/KL + gumbel sample (sums logit partials) --------
__global__ void sample_kernel(const float* __restrict__ U_t, float* __restrict__ losses_t,
                              const float* __restrict__ bp2, const float* __restrict__ bo2,
                              const float* __restrict__ actions_next) {
    const int row = blockIdx.x;
    const int tid = threadIdx.x;
    const int warp = tid >> 5, lane = tid & 31;
    __shared__ float klsh[8];

    if (actions_next && tid < NACT)
        g_ZA[(size_t)row * ZA_LD + 1024 + tid] = actions_next[row * NACT + tid];

    float klacc = 0.0f;
#pragma unroll
    for (int sg = 0; sg < 4; sg++) {
        const int s2 = warp * 4 + sg;
        const int col = s2 * 32 + lane;
        const int idx = row * 1024 + col;

        float pl = g_PP[0][idx] + g_PP[1][idx] + bp2[col];
        float ql = g_PP[2][idx] + g_PP[3][idx] + bo2[col];
        pl = fminf(fmaxf(pl, -20.0f), 20.0f);
        ql = fminf(fmaxf(ql, -20.0f), 20.0f);

        float pm = warp_max(pl);
        float pe = (float)exp((double)(pl - pm));
        float ps = warp_sum(pe);
        float pp = __fdiv_rn(pe, ps) * 0.99f + (0.01f / 32.0f);

        float qm = warp_max(ql);
        float qe = (float)exp((double)(ql - qm));
        float qs = warp_sum(qe);
        float qp = __fdiv_rn(qe, qs) * 0.99f + (0.01f / 32.0f);

        klacc += qp * (float)(log((double)(qp + 1e-8f)) - log((double)(pp + 1e-8f)));

        float u = U_t[idx];
        float gum = (float)(-log(-log((double)u + 1e-6) + 1e-6));
        float val = (float)log((double)fmaxf(qp, 1e-6f)) + gum;
        float bv = val; int bi = lane;
#pragma unroll
        for (int o = 16; o; o >>= 1) {
            float ov = __shfl_xor_sync(0xffffffffu, bv, o);
            int   oi = __shfl_xor_sync(0xffffffffu, bi, o);
            if (ov > bv || (ov == bv && oi < bi)) { bv = ov; bi = oi; }
        }
        float y = (lane == bi) ? 1.0f : 0.0f;
        float z = __fsub_rn(__fadd_rn(y, qp), qp);
        g_ZA[(size_t)row * ZA_LD + col] = z;
    }

    float w = warp_sum(klacc);
    if (lane == 0) klsh[warp] = w;
    __syncthreads();
    if (tid == 0) {
        float kl = 0.0f;
#pragma unroll
        for (int i = 0; i < 8; i++) kl += klsh[i];
        float m = fmaxf(kl, 0.1f);
        losses_t[row] = 1.0f * m + 0.1f * m;
    }
}

// ---------------- launch ----------------
extern "C" void kernel_launch(void* const* d_in, const int* in_sizes, int n_in,
                              void* d_out, int out_size) {
    const float* b0       = (const float*)d_in[0];
    const float* z0       = (const float*)d_in[1];
    const float* actions  = (const float*)d_in[2];
    const float* obs      = (const float*)d_in[3];
    const float* u_noise  = (const float*)d_in[4];
    const float* Wi1      = (const float*)d_in[5];
    const float* bi1      = (const float*)d_in[6];
    const float* Wi2      = (const float*)d_in[7];
    const float* bi2      = (const float*)d_in[8];
    const float* Wg       = (const float*)d_in[9];
    const float* ln_scale = (const float*)d_in[10];
    const float* ln_bias  = (const float*)d_in[11];
    const float* Wo1      = (const float*)d_in[12];
    const float* bo1      = (const float*)d_in[13];
    const float* Wo2      = (const float*)d_in[14];
    const float* bo2      = (const float*)d_in[15];
    const float* Wp1      = (const float*)d_in[16];
    const float* bp1      = (const float*)d_in[17];
    const float* Wp2      = (const float*)d_in[18];
    const float* bp2      = (const float*)d_in[19];
    float* out = (float*)d_out;

    float *pZA, *pH1, *pIB, *pHP, *pHO, *pWi1p, *pPP, *pGG;
    cudaGetSymbolAddress((void**)&pZA, g_ZA);
    cudaGetSymbolAddress((void**)&pH1, g_H1);
    cudaGetSymbolAddress((void**)&pIB, g_IB);
    cudaGetSymbolAddress((void**)&pHP, g_HP);
    cudaGetSymbolAddress((void**)&pHO, g_HO);
    cudaGetSymbolAddress((void**)&pWi1p, g_Wi1p);
    cudaGetSymbolAddress((void**)&pPP, g_PP);
    cudaGetSymbolAddress((void**)&pGG, g_GG);

    float* PP[4] = { pPP, pPP + NB * 1024, pPP + 2 * NB * 1024, pPP + 3 * NB * 1024 };
    float* GG[2] = { pGG, pGG + NB * GDIM };
    const float* belief = pIB + 1024;

    init_kernel<<<(NB * 1024 + 255) / 256, 256>>>(z0, b0, actions);
    padw_kernel<<<(WI1_K * 1024 + 255) / 256, 256>>>(Wi1);

    const dim3 gS4(16, 4, 4);   // N=1024, split-4 (or 2x split-2 pairs): 256 blocks
    const dim3 gG2(48, 4, 2);   // N=3072, split-2: 384 blocks
    const dim3 gF(256, 1, 1);   // fuse: 256 blk x 256 thr x float4 = 262144 floats
    const dim3 gF2(256, 2, 1);

    for (int t = 0; t < NT; t++) {
        const float* obs_t = obs + (size_t)t * NB * 1024;

        // ---- imagine layer 1: ZA @ Wi1p, K=1040, split 272/256/256/256 ----
        {
            GP a{pZA, ZA_LD, pZA, ZA_LD, WI1_K, pWi1p, 1024, PP[0], 1024, 0,   272};
            GP b{pZA, ZA_LD, pZA, ZA_LD, WI1_K, pWi1p, 1024, PP[1], 1024, 272, 528};
            GP c{pZA, ZA_LD, pZA, ZA_LD, WI1_K, pWi1p, 1024, PP[2], 1024, 528, 784};
            GP d{pZA, ZA_LD, pZA, ZA_LD, WI1_K, pWi1p, 1024, PP[3], 1024, 784, 1040};
            gemm7_kernel<<<gS4, 256>>>(a, b, c, d);
        }
        fuse4_kernel<<<gF, 256>>>(bi1, pH1, 1024, 1);

        // ---- imagine layer 2: H1 @ Wi2, K=1024, split4 ----
        {
            GP a{pH1, 1024, pH1, 1024, 1024, Wi2, 1024, PP[0], 1024, 0,   256};
            GP b{pH1, 1024, pH1, 1024, 1024, Wi2, 1024, PP[1], 1024, 256, 512};
            GP c{pH1, 1024, pH1, 1024, 1024, Wi2, 1024, PP[2], 1024, 512, 768};
            GP d{pH1, 1024, pH1, 1024, 1024, Wi2, 1024, PP[3], 1024, 768, 1024};
            gemm7_kernel<<<gS4, 256>>>(a, b, c, d);
        }
        fuse4_kernel<<<gF, 256>>>(bi2, pIB, 2048, 0);

        // ---- GRU gates: IB @ Wg, K=2048, N=3072, split2 ----
        {
            GP a{pIB, 2048, pIB, 2048, 2048, Wg, 3072, GG[0], 3072, 0,    1024};
            GP b{pIB, 2048, pIB, 2048, 2048, Wg, 3072, GG[1], 3072, 1024, 2048};
            gemm7_kernel<<<gG2, 256>>>(a, b, a, b);
        }
        lngru_kernel<<<NB, 256>>>(ln_scale, ln_bias);

        // ---- prior L1 (split2) || posterior L1 (split2) ----
        {
            GP a{belief, 2048, belief, 2048, 1024, Wp1, 1024, PP[0], 1024, 0,    512};
            GP b{belief, 2048, belief, 2048, 1024, Wp1, 1024, PP[1], 1024, 512,  1024};
            GP c{obs_t,  1024, belief, 2048, 1024, Wo1, 1024, PP[2], 1024, 0,    1024};
            GP d{obs_t,  1024, belief, 2048, 1024, Wo1, 1024, PP[3], 1024, 1024, 2048};
            gemm7_kernel<<<gS4, 256>>>(a, b, c, d);
        }
        fuse22_kernel<<<gF2, 256>>>(bp1, bo1);

        // ---- prior L2 (split2) || posterior L2 (split2) ----
        {
            GP a{pHP, 1024, pHP, 1024, 1024, Wp2, 1024, PP[0], 1024, 0,   512};
            GP b{pHP, 1024, pHP, 1024, 1024, Wp2, 1024, PP[1], 1024, 512, 1024};
            GP c{pHO, 1024, pHO, 1024, 1024, Wo2, 1024, PP[2], 1024, 0,   512};
            GP d{pHO, 1024, pHO, 1024, 1024, Wo2, 1024, PP[3], 1024, 512, 1024};
            gemm7_kernel<<<gS4, 256>>>(a, b, c, d);
        }

        // ---- probs + KL + gumbel sample (+ stage next actions) ----
        const float* an = (t + 1 < NT) ? (actions + (size_t)(t + 1) * NB * NACT) : nullptr;
        sample_kernel<<<NB, 256>>>(u_noise + (size_t)t * NB * 1024, out + (size_t)t * NB,
                                   bp2, bo2, an);
    }
}